// round 8
// baseline (speedup 1.0000x reference)
#include <cuda_runtime.h>
#include <cuda_bf16.h>
#include <cstdint>

// TiThTe: B=4096 independent 3-state RC thermal ODEs, Euler scan over T=8760
// steps with tame() soft-clip. Single-warp latency/issue bound.
// R7: warp-specialized blocks (128 thr): warp 0 computes the scan and writes
// one STS.128/step into a double-buffered smem ring (CHUNK=24 steps); warps
// 1-3 drain the ring to GMEM with coalesced streaming STG.32. This removes
// ~15 cyc/step of STG issue occupancy from the compute warp's SMSP.

#define TAME_C  100000.0f
#define TAME_SQ 1.0e10f
#define CHUNK   24

__device__ __forceinline__ float rsq_approx(float x) {
    float y;
    asm("rsqrt.approx.f32 %0, %1;" : "=f"(y) : "f"(x));
    return y;
}
__device__ __forceinline__ void nb_sync(int id) {
    asm volatile("bar.sync %0, 128;" :: "r"(id) : "memory");
}
__device__ __forceinline__ void nb_arrive(int id) {
    asm volatile("bar.arrive %0, 128;" :: "r"(id) : "memory");
}
__device__ __forceinline__ float decode_dt(const int* dtp) {
    int dv = dtp[0];
    return (dv > 0 && dv < (1 << 23)) ? (float)dv : __int_as_float(dv);
}

// ---------------- fast path: T % 24 == 0, B % 32 == 0 ----------------

__global__ void __launch_bounds__(128, 1)
tithte_ws(const float* __restrict__ state0,
          const float* __restrict__ params,
          const float* __restrict__ ext,     // (T,3): T_out, heatPower, solarGains
          const int*   __restrict__ dtp,
          float* __restrict__ out,           // (T,B,3)
          int B, int T)
{
    __shared__ float4 buf[2][CHUNK][32];     // 24 KB double buffer

    int tid  = threadIdx.x;
    int lane = tid & 31;
    int wid  = tid >> 5;
    int b0   = blockIdx.x * 32;
    int nchunks = T / CHUNK;

    if (wid == 0) {
        // ---- compute warp: one system per lane ----
        int b = b0 + lane;
        float dtf = decode_dt(dtp);

        float Tin = state0[b * 3 + 0];
        float Th  = state0[b * 3 + 1];
        float Te  = state0[b * 3 + 2];

        float C1 = params[b * 6 + 0], R1 = params[b * 6 + 1];
        float C2 = params[b * 6 + 2], R2 = params[b * 6 + 3];
        float C3 = params[b * 6 + 4], R3 = params[b * 6 + 5];

        float k1  = dtf / C1;
        float nkA = -k1 / R1;
        float nkB = -k1 / R2;
        float cA0 = nkA + nkB;
        float cH0 = -nkB;
        float cE0 = -nkA;
        float k2  = dtf / C2;
        float kC  =  k2 / R2;
        float nkC = -kC;
        float k3  = dtf / C3;
        float kD  =  k3 / R1;
        float kE  =  k3 / R3;
        float cE2 = -(kD + kE);

#define STEP(To_, hp_, sg_, S_)                               \
        {                                                     \
            float f0 = (sg_) * k1;                            \
            float f1 = (hp_) * k2;                            \
            float f2 = (To_) * kE;                            \
            float u0 = fmaf(Tin, cA0, f0);                    \
            float v0 = fmaf(Th, cH0, Te * cE0);               \
            float x0 = u0 + v0;                               \
            float x1 = fmaf(Th, nkC, fmaf(Tin, kC, f1));      \
            float x2 = fmaf(Te, cE2, fmaf(Tin, kD, f2));      \
            float r0 = rsq_approx(fmaf(x0, x0, TAME_SQ));     \
            float r1 = rsq_approx(fmaf(x1, x1, TAME_SQ));     \
            float r2 = rsq_approx(fmaf(x2, x2, TAME_SQ));     \
            Tin = fmaf(x0 * TAME_C, r0, Tin);                 \
            Th  = fmaf(x1 * TAME_C, r1, Th);                  \
            Te  = fmaf(x2 * TAME_C, r2, Te);                  \
            sb[(S_) * 32] = make_float4(Tin, Th, Te, 0.0f);   \
        }

        const float4* e4 = (const float4*)ext;   // 4 steps = 12 floats = 3 float4
        int ng = T >> 2;                          // 4-step groups
        float4 c0 = __ldg(e4 + 0), c1 = __ldg(e4 + 1), c2 = __ldg(e4 + 2);
        float4 n0 = __ldg(e4 + 3), n1 = __ldg(e4 + 4), n2 = __ldg(e4 + 5);

        int g = 0;
        for (int ch = 0; ch < nchunks; ++ch) {
            int bi = ch & 1;
            if (ch >= 2) nb_sync(2 + bi);         // wait buffer drained
            float4* sb = &buf[bi][0][lane];
            #pragma unroll
            for (int gi = 0; gi < 6; ++gi) {
                int pg = g + 2; if (pg > ng - 1) pg = ng - 1;   // prefetch 8 steps ahead
                const float4* pp = e4 + (size_t)pg * 3;
                float4 p0 = __ldg(pp), p1 = __ldg(pp + 1), p2 = __ldg(pp + 2);

                STEP(c0.x, c0.y, c0.z, gi * 4 + 0);
                STEP(c0.w, c1.x, c1.y, gi * 4 + 1);
                STEP(c1.z, c1.w, c2.x, gi * 4 + 2);
                STEP(c2.y, c2.z, c2.w, gi * 4 + 3);

                c0 = n0; c1 = n1; c2 = n2;
                n0 = p0; n1 = p1; n2 = p2;
                ++g;
            }
            nb_arrive(0 + bi);                    // buffer full
        }
#undef STEP
    } else {
        // ---- storer warps: 96 threads, each owns one (system, component) ----
        int sid  = tid - 32;                      // 0..95
        int sys  = sid / 3;
        int comp = sid - sys * 3;
        const size_t stride = (size_t)B * 3;
        float* gp = out + (size_t)b0 * 3 + sid;   // coalesced across sid

        for (int ch = 0; ch < nchunks; ++ch) {
            int bi = ch & 1;
            nb_sync(0 + bi);                      // wait buffer full
            size_t tbase = (size_t)ch * CHUNK;
            #pragma unroll 6
            for (int s = 0; s < CHUNK; ++s) {
                float v = ((const float*)&buf[bi][s][sys])[comp];
                __stcs(gp + (tbase + s) * stride, v);
            }
            nb_arrive(2 + bi);                    // buffer free
        }
    }
}

// ---------------- generic fallback (any T, B) ----------------

__global__ void __launch_bounds__(32, 1)
tithte_fallback(const float* __restrict__ state0,
                const float* __restrict__ params,
                const float* __restrict__ ext,
                const int*   __restrict__ dtp,
                float* __restrict__ out,
                int B, int T)
{
    int b = blockIdx.x * blockDim.x + threadIdx.x;
    if (b >= B) return;
    float dtf = decode_dt(dtp);

    float Tin = state0[b * 3 + 0], Th = state0[b * 3 + 1], Te = state0[b * 3 + 2];
    float C1 = params[b * 6 + 0], R1 = params[b * 6 + 1];
    float C2 = params[b * 6 + 2], R2 = params[b * 6 + 3];
    float C3 = params[b * 6 + 4], R3 = params[b * 6 + 5];
    float k1 = dtf / C1, nkA = -k1 / R1, nkB = -k1 / R2;
    float cA0 = nkA + nkB, cH0 = -nkB, cE0 = -nkA;
    float k2 = dtf / C2, kC = k2 / R2, nkC = -kC;
    float k3 = dtf / C3, kD = k3 / R1, kE = k3 / R3, cE2 = -(kD + kE);

    float* op = out + (size_t)b * 3;
    const size_t stride = (size_t)B * 3;
    for (int t = 0; t < T; ++t) {
        float To = __ldg(ext + (size_t)t * 3 + 0);
        float hp = __ldg(ext + (size_t)t * 3 + 1);
        float sg = __ldg(ext + (size_t)t * 3 + 2);
        float f0 = sg * k1, f1 = hp * k2, f2 = To * kE;
        float u0 = fmaf(Tin, cA0, f0);
        float v0 = fmaf(Th, cH0, Te * cE0);
        float x0 = u0 + v0;
        float x1 = fmaf(Th, nkC, fmaf(Tin, kC, f1));
        float x2 = fmaf(Te, cE2, fmaf(Tin, kD, f2));
        float r0 = rsq_approx(fmaf(x0, x0, TAME_SQ));
        float r1 = rsq_approx(fmaf(x1, x1, TAME_SQ));
        float r2 = rsq_approx(fmaf(x2, x2, TAME_SQ));
        Tin = fmaf(x0 * TAME_C, r0, Tin);
        Th  = fmaf(x1 * TAME_C, r1, Th);
        Te  = fmaf(x2 * TAME_C, r2, Te);
        __stcs(op + 0, Tin);
        __stcs(op + 1, Th);
        __stcs(op + 2, Te);
        op += stride;
    }
}

extern "C" void kernel_launch(void* const* d_in, const int* in_sizes, int n_in,
                              void* d_out, int out_size)
{
    const float* state0 = (const float*)d_in[0];   // (B,3)
    const float* params = (const float*)d_in[1];   // (B,6)
    const float* ext    = (const float*)d_in[2];   // (T,3)
    const int*   dtp    = (const int*)d_in[3];     // scalar
    float* out = (float*)d_out;                    // (T,B,3)

    int B = in_sizes[0] / 3;
    int T = in_sizes[2] / 3;

    if ((T % CHUNK) == 0 && (B % 32) == 0 && T >= 48) {
        tithte_ws<<<B / 32, 128>>>(state0, params, ext, dtp, out, B, T);
    } else {
        tithte_fallback<<<(B + 31) / 32, 32>>>(state0, params, ext, dtp, out, B, T);
    }
}

// round 9
// speedup vs baseline: 1.1577x; 1.1577x over previous
#include <cuda_runtime.h>
#include <cuda_bf16.h>
#include <cstdint>

// TiThTe: B=4096 independent 3-state RC thermal ODEs, Euler scan over T=8760
// steps with tame() soft-clip. Single-warp latency/issue bound.
// R9: 2 systems per thread via packed fma.rn.f32x2 (Blackwell f32x2 pipe,
// PTX-only). Halves per-system FMA-rt and chain cost; MUFU rsqrt stays
// scalar (6/pair, the new binding pipe at 48 cyc/pair). Pair output is 24
// contiguous bytes -> 3x coalesced STG.64 instead of 6x STG.32.

#define TAME_C  100000.0f
#define TAME_SQ 1.0e10f

typedef unsigned long long u64;

__device__ __forceinline__ float rsq_approx(float x) {
    float y;
    asm("rsqrt.approx.f32 %0, %1;" : "=f"(y) : "f"(x));
    return y;
}
__device__ __forceinline__ u64 pk2(float a, float b) {
    u64 r;
    asm("mov.b64 %0, {%1, %2};" : "=l"(r) : "r"(__float_as_uint(a)), "r"(__float_as_uint(b)));
    return r;
}
__device__ __forceinline__ void up2(u64 v, float& a, float& b) {
    unsigned int x, y;
    asm("mov.b64 {%0, %1}, %2;" : "=r"(x), "=r"(y) : "l"(v));
    a = __uint_as_float(x); b = __uint_as_float(y);
}
__device__ __forceinline__ u64 fma2(u64 a, u64 b, u64 c) {
    u64 d;
    asm("fma.rn.f32x2 %0, %1, %2, %3;" : "=l"(d) : "l"(a), "l"(b), "l"(c));
    return d;
}
__device__ __forceinline__ u64 mul2(u64 a, u64 b) {
    u64 d;
    asm("mul.rn.f32x2 %0, %1, %2;" : "=l"(d) : "l"(a), "l"(b));
    return d;
}
__device__ __forceinline__ u64 add2(u64 a, u64 b) {
    u64 d;
    asm("add.rn.f32x2 %0, %1, %2;" : "=l"(d) : "l"(a), "l"(b));
    return d;
}
__device__ __forceinline__ float decode_dt(const int* dtp) {
    int dv = dtp[0];
    return (dv > 0 && dv < (1 << 23)) ? (float)dv : __int_as_float(dv);
}

// ---------------- fast path: B even; thread handles systems 2i, 2i+1 -------

__global__ void __launch_bounds__(32, 1)
tithte_f32x2(const float* __restrict__ state0,
             const float* __restrict__ params,
             const float* __restrict__ ext,    // (T,3): T_out, heatPower, solarGains
             const int*   __restrict__ dtp,
             float* __restrict__ out,          // (T,B,3)
             int B, int T)
{
    int i = blockIdx.x * blockDim.x + threadIdx.x;   // pair index
    int P = B >> 1;
    if (i >= P) return;
    int bA = 2 * i, bB = 2 * i + 1;

    float dtf = decode_dt(dtp);

    u64 Tin = pk2(state0[bA * 3 + 0], state0[bB * 3 + 0]);
    u64 Th  = pk2(state0[bA * 3 + 1], state0[bB * 3 + 1]);
    u64 Te  = pk2(state0[bA * 3 + 2], state0[bB * 3 + 2]);

    // Per-system coefficient computation, then pack.
    float k1s[2], k2s[2], kEs[2], cA0s[2], cH0s[2], cE0s[2], kCs[2], kDs[2], cE2s[2];
    #pragma unroll
    for (int s = 0; s < 2; ++s) {
        const float* pp = params + (size_t)(2 * i + s) * 6;
        float C1 = pp[0], R1 = pp[1], C2 = pp[2], R2 = pp[3], C3 = pp[4], R3 = pp[5];
        float k1 = dtf / C1, nkA = -k1 / R1, nkB = -k1 / R2;
        float k2 = dtf / C2, kC = k2 / R2;
        float k3 = dtf / C3, kD = k3 / R1, kE = k3 / R3;
        k1s[s] = k1;  k2s[s] = k2;  kEs[s] = kE;
        cA0s[s] = nkA + nkB;  cH0s[s] = -nkB;  cE0s[s] = -nkA;
        kCs[s] = kC;  kDs[s] = kD;  cE2s[s] = -(kD + kE);
    }
    u64 k1p  = pk2(k1s[0],  k1s[1]);
    u64 k2p  = pk2(k2s[0],  k2s[1]);
    u64 kEp  = pk2(kEs[0],  kEs[1]);
    u64 cA0p = pk2(cA0s[0], cA0s[1]);
    u64 cH0p = pk2(cH0s[0], cH0s[1]);
    u64 cE0p = pk2(cE0s[0], cE0s[1]);
    u64 kCp  = pk2(kCs[0],  kCs[1]);
    u64 nkCp = pk2(-kCs[0], -kCs[1]);
    u64 kDp  = pk2(kDs[0],  kDs[1]);
    u64 cE2p = pk2(cE2s[0], cE2s[1]);
    const u64 TSp = pk2(TAME_SQ, TAME_SQ);
    const u64 TCp = pk2(TAME_C,  TAME_C);

    float* op = out + (size_t)i * 6;           // 24B, 8-aligned; stride 8-aligned
    const size_t stride = (size_t)B * 3;

#define STEPP(To_, hp_, sg_)                                      \
    {                                                             \
        u64 f0 = mul2(pk2((sg_), (sg_)), k1p);                    \
        u64 f1 = mul2(pk2((hp_), (hp_)), k2p);                    \
        u64 f2 = mul2(pk2((To_), (To_)), kEp);                    \
        u64 u0 = fma2(Tin, cA0p, f0);                             \
        u64 v0 = fma2(Th, cH0p, mul2(Te, cE0p));                  \
        u64 x0 = add2(u0, v0);                                    \
        u64 x1 = fma2(Th, nkCp, fma2(Tin, kCp, f1));              \
        u64 x2 = fma2(Te, cE2p, fma2(Tin, kDp, f2));              \
        u64 q0 = fma2(x0, x0, TSp);                               \
        u64 q1 = fma2(x1, x1, TSp);                               \
        u64 q2 = fma2(x2, x2, TSp);                               \
        float qa, qb, qc, qd, qe, qf;                             \
        up2(q0, qa, qb); up2(q1, qc, qd); up2(q2, qe, qf);        \
        u64 r0 = pk2(rsq_approx(qa), rsq_approx(qb));             \
        u64 r1 = pk2(rsq_approx(qc), rsq_approx(qd));             \
        u64 r2 = pk2(rsq_approx(qe), rsq_approx(qf));             \
        Tin = fma2(mul2(x0, TCp), r0, Tin);                       \
        Th  = fma2(mul2(x1, TCp), r1, Th);                        \
        Te  = fma2(mul2(x2, TCp), r2, Te);                        \
        float a0, a1, a2, b0, b1, b2;                             \
        up2(Tin, a0, b0); up2(Th, a1, b1); up2(Te, a2, b2);       \
        __stcs((float2*)(op + 0), make_float2(a0, a1));           \
        __stcs((float2*)(op + 2), make_float2(a2, b0));           \
        __stcs((float2*)(op + 4), make_float2(b1, b2));           \
        op += stride;                                             \
    }

    int ng = T >> 2;            // 4-step groups
    if (ng > 0) {
        const float4* e4 = (const float4*)ext;   // 4 rows = 12 floats = 3 float4
        float4 c0 = __ldg(e4 + 0), c1 = __ldg(e4 + 1), c2 = __ldg(e4 + 2);
        int j1 = (ng > 1) ? 3 : 0;
        float4 n0 = __ldg(e4 + j1), n1 = __ldg(e4 + j1 + 1), n2 = __ldg(e4 + j1 + 2);

        for (int g = 0; g < ng; ++g) {
            int pg = g + 2; if (pg > ng - 1) pg = ng - 1;   // prefetch 8 steps ahead
            const float4* pp = e4 + (size_t)pg * 3;
            float4 p0 = __ldg(pp), p1 = __ldg(pp + 1), p2 = __ldg(pp + 2);

            STEPP(c0.x, c0.y, c0.z);
            STEPP(c0.w, c1.x, c1.y);
            STEPP(c1.z, c1.w, c2.x);
            STEPP(c2.y, c2.z, c2.w);

            c0 = n0; c1 = n1; c2 = n2;
            n0 = p0; n1 = p1; n2 = p2;
        }
    }
    for (int t = ng << 2; t < T; ++t) {          // tail (T % 4)
        float To = __ldg(ext + (size_t)t * 3 + 0);
        float hp = __ldg(ext + (size_t)t * 3 + 1);
        float sg = __ldg(ext + (size_t)t * 3 + 2);
        STEPP(To, hp, sg);
    }
#undef STEPP
}

// ---------------- generic scalar fallback (any B, T) ----------------

__global__ void __launch_bounds__(32, 1)
tithte_fallback(const float* __restrict__ state0,
                const float* __restrict__ params,
                const float* __restrict__ ext,
                const int*   __restrict__ dtp,
                float* __restrict__ out,
                int B, int T)
{
    int b = blockIdx.x * blockDim.x + threadIdx.x;
    if (b >= B) return;
    float dtf = decode_dt(dtp);

    float Tin = state0[b * 3 + 0], Th = state0[b * 3 + 1], Te = state0[b * 3 + 2];
    float C1 = params[b * 6 + 0], R1 = params[b * 6 + 1];
    float C2 = params[b * 6 + 2], R2 = params[b * 6 + 3];
    float C3 = params[b * 6 + 4], R3 = params[b * 6 + 5];
    float k1 = dtf / C1, nkA = -k1 / R1, nkB = -k1 / R2;
    float cA0 = nkA + nkB, cH0 = -nkB, cE0 = -nkA;
    float k2 = dtf / C2, kC = k2 / R2, nkC = -kC;
    float k3 = dtf / C3, kD = k3 / R1, kE = k3 / R3, cE2 = -(kD + kE);

    float* op = out + (size_t)b * 3;
    const size_t stride = (size_t)B * 3;
    for (int t = 0; t < T; ++t) {
        float To = __ldg(ext + (size_t)t * 3 + 0);
        float hp = __ldg(ext + (size_t)t * 3 + 1);
        float sg = __ldg(ext + (size_t)t * 3 + 2);
        float f0 = sg * k1, f1 = hp * k2, f2 = To * kE;
        float u0 = fmaf(Tin, cA0, f0);
        float v0 = fmaf(Th, cH0, Te * cE0);
        float x0 = u0 + v0;
        float x1 = fmaf(Th, nkC, fmaf(Tin, kC, f1));
        float x2 = fmaf(Te, cE2, fmaf(Tin, kD, f2));
        float r0 = rsq_approx(fmaf(x0, x0, TAME_SQ));
        float r1 = rsq_approx(fmaf(x1, x1, TAME_SQ));
        float r2 = rsq_approx(fmaf(x2, x2, TAME_SQ));
        Tin = fmaf(x0 * TAME_C, r0, Tin);
        Th  = fmaf(x1 * TAME_C, r1, Th);
        Te  = fmaf(x2 * TAME_C, r2, Te);
        __stcs(op + 0, Tin);
        __stcs(op + 1, Th);
        __stcs(op + 2, Te);
        op += stride;
    }
}

extern "C" void kernel_launch(void* const* d_in, const int* in_sizes, int n_in,
                              void* d_out, int out_size)
{
    const float* state0 = (const float*)d_in[0];   // (B,3)
    const float* params = (const float*)d_in[1];   // (B,6)
    const float* ext    = (const float*)d_in[2];   // (T,3)
    const int*   dtp    = (const int*)d_in[3];     // scalar
    float* out = (float*)d_out;                    // (T,B,3)

    int B = in_sizes[0] / 3;
    int T = in_sizes[2] / 3;

    if ((B & 1) == 0) {
        int P = B >> 1;
        tithte_f32x2<<<(P + 31) / 32, 32>>>(state0, params, ext, dtp, out, B, T);
    } else {
        tithte_fallback<<<(B + 31) / 32, 32>>>(state0, params, ext, dtp, out, B, T);
    }
}

// round 13
// speedup vs baseline: 1.8674x; 1.6131x over previous
#include <cuda_runtime.h>
#include <cuda_bf16.h>
#include <cstdint>

// TiThTe: B=4096 independent 3-state RC thermal ODEs, Euler scan over T=8760
// steps with tame() soft-clip. Wall time = T * (per-thread step cycles);
// one system per thread, 1 warp/SM -> purely latency/issue bound.
// R10 vs R6 (438.7us): 8-step blocks with ping-pong X/Y prefetch register
// sets (zero rotation MOVs), templated stride (immediate-offset STG, no
// per-step pointer math), x0 fma-chain ordered so Te (behind the 3rd MUFU)
// enters last. Target steady-state period ~52 cyc/step.

#define TAME_C  100000.0f
#define TAME_SQ 1.0e10f

__device__ __forceinline__ float rsq_approx(float x) {
    float y;
    asm("rsqrt.approx.f32 %0, %1;" : "=f"(y) : "f"(x));
    return y;
}
__device__ __forceinline__ float decode_dt(const int* dtp) {
    int dv = dtp[0];
    return (dv > 0 && dv < (1 << 23)) ? (float)dv : __int_as_float(dv);
}

// BLIT > 0: compile-time B (stride folds into STG immediate offsets).
template<int BLIT>
__global__ void __launch_bounds__(32, 1)
tithte8(const float* __restrict__ state0,
        const float* __restrict__ params,
        const float* __restrict__ ext,     // (T,3): T_out, heatPower, solarGains
        const int*   __restrict__ dtp,
        float* __restrict__ out,           // (T,B,3)
        int B, int T)
{
    int b = blockIdx.x * 32 + threadIdx.x;
    if (b >= B) return;

    const size_t stride = (size_t)((BLIT > 0) ? BLIT : B) * 3;

    float dtf = decode_dt(dtp);

    float Tin = state0[b * 3 + 0];
    float Th  = state0[b * 3 + 1];
    float Te  = state0[b * 3 + 2];

    float C1 = params[b * 6 + 0], R1 = params[b * 6 + 1];
    float C2 = params[b * 6 + 2], R2 = params[b * 6 + 3];
    float C3 = params[b * 6 + 4], R3 = params[b * 6 + 5];

    float k1  = dtf / C1;
    float nkA = -k1 / R1;
    float nkB = -k1 / R2;
    float cA0 = nkA + nkB;
    float cH0 = -nkB;
    float cE0 = -nkA;
    float k2  = dtf / C2;
    float kC  =  k2 / R2;
    float nkC = -kC;
    float k3  = dtf / C3;
    float kD  =  k3 / R1;
    float kE  =  k3 / R3;
    float cE2 = -(kD + kE);

    float* op = out + (size_t)b * 3;

    // x0 chain ordered so Te (latest state, behind 3rd MUFU) enters last.
#define STEP(To_, hp_, sg_, S_)                                        \
    {                                                                  \
        float f0 = (sg_) * k1;                                         \
        float f1 = (hp_) * k2;                                         \
        float f2 = (To_) * kE;                                         \
        float x0 = fmaf(Te, cE0, fmaf(Th, cH0, fmaf(Tin, cA0, f0)));   \
        float x1 = fmaf(Th, nkC, fmaf(Tin, kC, f1));                   \
        float x2 = fmaf(Te, cE2, fmaf(Tin, kD, f2));                   \
        float r0 = rsq_approx(fmaf(x0, x0, TAME_SQ));                  \
        float r1 = rsq_approx(fmaf(x1, x1, TAME_SQ));                  \
        float r2 = rsq_approx(fmaf(x2, x2, TAME_SQ));                  \
        Tin = fmaf(x0 * TAME_C, r0, Tin);                              \
        Th  = fmaf(x1 * TAME_C, r1, Th);                               \
        Te  = fmaf(x2 * TAME_C, r2, Te);                               \
        __stcs(op + (size_t)(S_) * stride + 0, Tin);                   \
        __stcs(op + (size_t)(S_) * stride + 1, Th);                    \
        __stcs(op + (size_t)(S_) * stride + 2, Te);                    \
    }

    // 8 steps = 24 ext floats = 6 float4.
#define PROC8(a0, a1, a2, a3, a4, a5)                                  \
    STEP(a0.x, a0.y, a0.z, 0)  STEP(a0.w, a1.x, a1.y, 1)               \
    STEP(a1.z, a1.w, a2.x, 2)  STEP(a2.y, a2.z, a2.w, 3)               \
    STEP(a3.x, a3.y, a3.z, 4)  STEP(a3.w, a4.x, a4.y, 5)               \
    STEP(a4.z, a4.w, a5.x, 6)  STEP(a5.y, a5.z, a5.w, 7)               \
    op += 8 * stride;

    int nb8 = T >> 3;
    const float4* e4 = (const float4*)ext;

    if (nb8 > 0) {
        // X holds even blocks, Y odd blocks; refill right after consumption
        // (next needed 8 steps ~ 400+ cycles later -> LDG latency hidden).
        float4 X0, X1, X2, X3, X4, X5, Y0, Y1, Y2, Y3, Y4, Y5;
        {
            const float4* p0 = e4;
            X0 = __ldg(p0 + 0); X1 = __ldg(p0 + 1); X2 = __ldg(p0 + 2);
            X3 = __ldg(p0 + 3); X4 = __ldg(p0 + 4); X5 = __ldg(p0 + 5);
            int i1 = (nb8 > 1) ? 1 : 0;
            const float4* p1 = e4 + (size_t)i1 * 6;
            Y0 = __ldg(p1 + 0); Y1 = __ldg(p1 + 1); Y2 = __ldg(p1 + 2);
            Y3 = __ldg(p1 + 3); Y4 = __ldg(p1 + 4); Y5 = __ldg(p1 + 5);
        }

        int npairs = nb8 >> 1;
        for (int p = 0; p < npairs; ++p) {
            int ia = 2 * p + 2; if (ia > nb8 - 1) ia = nb8 - 1;
            int ib = 2 * p + 3; if (ib > nb8 - 1) ib = nb8 - 1;

            PROC8(X0, X1, X2, X3, X4, X5)
            {
                const float4* pa = e4 + (size_t)ia * 6;
                X0 = __ldg(pa + 0); X1 = __ldg(pa + 1); X2 = __ldg(pa + 2);
                X3 = __ldg(pa + 3); X4 = __ldg(pa + 4); X5 = __ldg(pa + 5);
            }
            PROC8(Y0, Y1, Y2, Y3, Y4, Y5)
            {
                const float4* pb = e4 + (size_t)ib * 6;
                Y0 = __ldg(pb + 0); Y1 = __ldg(pb + 1); Y2 = __ldg(pb + 2);
                Y3 = __ldg(pb + 3); Y4 = __ldg(pb + 4); Y5 = __ldg(pb + 5);
            }
        }
        if (nb8 & 1) {
            PROC8(X0, X1, X2, X3, X4, X5)
        }
    }

    // Tail: T % 8 steps.
    for (int t = nb8 << 3; t < T; ++t) {
        float To = __ldg(ext + (size_t)t * 3 + 0);
        float hp = __ldg(ext + (size_t)t * 3 + 1);
        float sg = __ldg(ext + (size_t)t * 3 + 2);
        STEP(To, hp, sg, 0)
        op += stride;
    }
#undef PROC8
#undef STEP
}

extern "C" void kernel_launch(void* const* d_in, const int* in_sizes, int n_in,
                              void* d_out, int out_size)
{
    const float* state0 = (const float*)d_in[0];   // (B,3)
    const float* params = (const float*)d_in[1];   // (B,6)
    const float* ext    = (const float*)d_in[2];   // (T,3)
    const int*   dtp    = (const int*)d_in[3];     // scalar
    float* out = (float*)d_out;                    // (T,B,3)

    int B = in_sizes[0] / 3;
    int T = in_sizes[2] / 3;
    int grid = (B + 31) / 32;

    if (B == 4096) {
        tithte8<4096><<<grid, 32>>>(state0, params, ext, dtp, out, B, T);
    } else {
        tithte8<0><<<grid, 32>>>(state0, params, ext, dtp, out, B, T);
    }
}